// round 13
// baseline (speedup 1.0000x reference)
#include <cuda_runtime.h>
#include <cuda_bf16.h>
#include <cstdint>

// Problem constants
#define NB   4
#define TT   1024
#define VV   32000
#define HH   512
#define MROWS (NB*TT)            // 4096
#define YSIZE ((size_t)MROWS*VV) // 131072000

#define CLU  16                  // cluster size per direction
#define JPC  (HH/CLU)            // 32 j-columns per CTA
#define KSL  8                   // K-slices per CTA
#define ISL  (HH/KSL)            // 64 i-elements per slice

// Scratch (allocation-free rule -> __device__ globals)
__device__ float g_xh[2u*TT*NB*HH];       // [dir][s][n][j] 16 MB
__device__ float g_z[(size_t)MROWS*2*HH]; // [m][k] tf32-rounded A-matrix, 16 MB
__device__ float g_Wt[(size_t)VV*1024];   // Wout^T [n][k] tf32-rounded, 128 MB
__device__ float g_rowsum[MROWS];         // softmax denominators

// ---------------------------------------------------------------------------
// helpers
// ---------------------------------------------------------------------------
__device__ __forceinline__ unsigned smem_u32(const void* p)
{
    unsigned a;
    asm("{ .reg .u64 t; cvta.to.shared.u64 t, %1; cvt.u32.u64 %0, t; }"
        : "=r"(a) : "l"(p));
    return a;
}

__device__ __forceinline__ uint32_t swz(uint32_t o) { return o ^ ((o >> 3) & 0x70); }

__device__ __forceinline__ float tf32r(float f)      // round-to-nearest tf32
{
    uint32_t r;
    asm("cvt.rna.tf32.f32 %0, %1;" : "=r"(r) : "f"(f));
    return __uint_as_float(r);
}

__device__ __forceinline__ void cp16(uint32_t saddr, const void* gaddr)
{
    asm volatile("cp.async.cg.shared.global [%0], [%1], 16;"
                 :: "r"(saddr), "l"(gaddr) : "memory");
}
__device__ __forceinline__ void cp_commit()
{
    asm volatile("cp.async.commit_group;" ::: "memory");
}
__device__ __forceinline__ void cp_wait1()
{
    asm volatile("cp.async.wait_group 1;" ::: "memory");
}
__device__ __forceinline__ void cp_wait0()
{
    asm volatile("cp.async.wait_group 0;" ::: "memory");
}

__device__ __forceinline__ void ldsm4(uint32_t addr, uint32_t& r0, uint32_t& r1,
                                      uint32_t& r2, uint32_t& r3)
{
    asm volatile("ldmatrix.sync.aligned.m8n8.x4.shared.b16 {%0,%1,%2,%3}, [%4];"
                 : "=r"(r0), "=r"(r1), "=r"(r2), "=r"(r3) : "r"(addr));
}

__device__ __forceinline__ void mma8(float* d, const uint32_t* a,
                                     uint32_t b0, uint32_t b1)
{
    asm volatile("mma.sync.aligned.m16n8k8.row.col.f32.tf32.tf32.f32 "
                 "{%0,%1,%2,%3}, {%4,%5,%6,%7}, {%8,%9}, {%0,%1,%2,%3};"
                 : "+f"(d[0]), "+f"(d[1]), "+f"(d[2]), "+f"(d[3])
                 : "r"(a[0]), "r"(a[1]), "r"(a[2]), "r"(a[3]), "r"(b0), "r"(b1));
}

__device__ __forceinline__ void mbar_wait_cluster(uint32_t a, uint32_t ph)
{
    asm volatile("{\n\t.reg .pred P;\n\tWL%=:\n\t"
                 "mbarrier.try_wait.parity.acquire.cluster.shared::cta.b64 P, [%0], %1, 0x989680;\n\t"
                 "@!P bra WL%=;\n\t}"
                 :: "r"(a), "r"(ph) : "memory");
}

// ---------------------------------------------------------------------------
// Kernel 1: embedding gather
// ---------------------------------------------------------------------------
__global__ __launch_bounds__(128)
void gather_kernel(const int* __restrict__ x,
                   const float* __restrict__ Ef,
                   const float* __restrict__ Eb)
{
    int b   = blockIdx.x;
    int dir = b >> 12;
    int s   = (b >> 2) & 1023;
    int n   = b & 3;
    int t   = dir ? (TT - 1 - s) : s;
    int tok = x[n * TT + t];
    const float4* src = (const float4*)((dir ? Eb : Ef) + (size_t)tok * HH);
    float4* dst = (float4*)(g_xh + ((size_t)(dir * TT + s) * NB + n) * HH);
    dst[threadIdx.x] = src[threadIdx.x];
}

// ---------------------------------------------------------------------------
// Kernel 1b: transpose Wout[k][n] -> g_Wt[n][k], tf32-rounded at write
// ---------------------------------------------------------------------------
__global__ __launch_bounds__(256)
void transpose_kernel(const float* __restrict__ Wout)
{
    __shared__ float t[32][33];
    int n0 = blockIdx.x * 32;
    int k0 = blockIdx.y * 32;
    int tx = threadIdx.x & 31, ty = threadIdx.x >> 5;
#pragma unroll
    for (int r = 0; r < 32; r += 8)
        t[ty + r][tx] = Wout[(size_t)(k0 + ty + r) * VV + n0 + tx];
    __syncthreads();
#pragma unroll
    for (int r = 0; r < 32; r += 8)
        g_Wt[(size_t)(n0 + ty + r) * 1024 + k0 + tx] = tf32r(t[tx][ty + r]);
}

// ---------------------------------------------------------------------------
// Kernel 1c: zero the softmax row-sum accumulators
// ---------------------------------------------------------------------------
__global__ __launch_bounds__(1024)
void zero_kernel()
{
    g_rowsum[blockIdx.x * 1024 + threadIdx.x] = 0.f;
}

// ---------------------------------------------------------------------------
// Kernel 2: bidirectional RNN scan, cluster-of-16 per direction.
// Weights pre-packed as f32x2 pairs (no per-iteration mov.b64).
// ---------------------------------------------------------------------------
__global__ __cluster_dims__(CLU, 1, 1) __launch_bounds__(256, 1)
void rnn_kernel(const float* __restrict__ Wh_f, const float* __restrict__ Wh_b,
                const float* __restrict__ bh_f, const float* __restrict__ bh_b,
                float* __restrict__ out)
{
    __shared__ float    h_s[2][HH][NB];       // [buf][j][n], 16 KB
    __shared__ float    red[2][KSL][JPC][4];  // [buf][kslice][jj][n], 8 KB
    __shared__ uint64_t mbar[2];

    int tid = threadIdx.x;
    int jj  = tid & 31;
    int ks  = tid >> 5;            // 0..7
    unsigned crank;
    asm("mov.u32 %0, %%cluster_ctarank;" : "=r"(crank));
    int dir = blockIdx.x >> 4;
    int j   = (int)crank * JPC + jj;

    const float* Wh = dir ? Wh_b : Wh_f;
    const float* bh = dir ? bh_b : bh_f;

    // register-resident packed weight slice: {w,w} for Wh[ks*64+u][j]
    uint64_t wpk[ISL];
#pragma unroll
    for (int u = 0; u < ISL; ++u) {
        uint32_t wu = __float_as_uint(Wh[(size_t)(ks * ISL + u) * HH + j]);
        asm("mov.b64 %0, {%1, %1};" : "=l"(wpk[u]) : "r"(wu));
    }
    float bhv = bh[j];

    // init: zero h buffer 0, init + pre-arm both mbarriers
    for (int i = tid; i < HH * NB; i += 256) ((float*)h_s[0])[i] = 0.f;
    if (tid == 0) {
        uint32_t m0 = smem_u32(&mbar[0]), m1 = smem_u32(&mbar[1]);
        asm volatile("mbarrier.init.shared.b64 [%0], 1;" :: "r"(m0) : "memory");
        asm volatile("mbarrier.init.shared.b64 [%0], 1;" :: "r"(m1) : "memory");
        asm volatile("fence.mbarrier_init.release.cluster;" ::: "memory");
        asm volatile("mbarrier.arrive.expect_tx.shared.b64 _, [%0], %1;"
                     :: "r"(m0), "r"(8192u) : "memory");
        asm volatile("mbarrier.arrive.expect_tx.shared.b64 _, [%0], %1;"
                     :: "r"(m1), "r"(8192u) : "memory");
    }
    __syncthreads();
    asm volatile("barrier.cluster.arrive.aligned;" ::: "memory");
    asm volatile("barrier.cluster.wait.aligned;"   ::: "memory");

    // remote base addresses for all 16 cluster CTAs
    uint32_t hloc = smem_u32(&h_s[0][0][0]);
    uint32_t mloc = smem_u32(&mbar[0]);
    uint32_t rh[CLU], rm[CLU];
#pragma unroll
    for (int c = 0; c < CLU; ++c) {
        asm("mapa.shared::cluster.u32 %0, %1, %2;" : "=r"(rh[c]) : "r"(hloc), "r"(c));
        asm("mapa.shared::cluster.u32 %0, %1, %2;" : "=r"(rm[c]) : "r"(mloc), "r"(c));
    }

    const float* xh_base = g_xh + (size_t)dir * TT * NB * HH;
    uint32_t ph0 = 0, ph1 = 0;

    for (int s = 0; s < TT; ++s) {
        int rb = s & 1;        // h read buffer / red buffer
        int wb = rb ^ 1;       // h write buffer

        if (s > 0) {
            uint32_t mb = mloc + (uint32_t)rb * 8;
            mbar_wait_cluster(mb, rb ? ph1 : ph0);
            if (tid == 0)
                asm volatile("mbarrier.arrive.expect_tx.shared.b64 _, [%0], %1;"
                             :: "r"(mb), "r"(8192u) : "memory");
            if (rb) ph1 ^= 1; else ph0 ^= 1;
        }

        // prefetch xh for phase 2 (threads 0..31 only)
        float xv0 = 0.f, xv1 = 0.f, xv2 = 0.f, xv3 = 0.f;
        if (tid < JPC) {
            const float* xp = xh_base + (size_t)s * NB * HH + j;
            xv0 = xp[0]; xv1 = xp[HH]; xv2 = xp[2 * HH]; xv3 = xp[3 * HH];
        }

        // phase 1: packed partial dot for 4 batch rows over 64 K-elements
        uint64_t a01 = 0ull, a23 = 0ull;
        uint32_t hb = hloc + (uint32_t)rb * (HH * NB * 4) + (uint32_t)(ks * ISL) * 16;
#pragma unroll
        for (int u = 0; u < ISL; ++u) {
            uint64_t h01, h23;
            asm("ld.shared.v2.b64 {%0,%1}, [%2];"
                : "=l"(h01), "=l"(h23) : "r"(hb + u * 16));
            asm("fma.rn.f32x2 %0, %1, %2, %0;" : "+l"(a01) : "l"(h01), "l"(wpk[u]));
            asm("fma.rn.f32x2 %0, %1, %2, %0;" : "+l"(a23) : "l"(h23), "l"(wpk[u]));
        }
        {
            uint32_t rw = smem_u32(&red[rb][ks][jj][0]);
            asm volatile("st.shared.v2.b64 [%0], {%1,%2};"
                         :: "r"(rw), "l"(a01), "l"(a23) : "memory");
        }
        __syncthreads();

        // phase 2: thread jj (tid<32) handles column j, all 4 batches
        if (tid < JPC) {
            float4 p0 = *(const float4*)&red[rb][0][jj][0];
            float4 p1 = *(const float4*)&red[rb][1][jj][0];
            float4 p2 = *(const float4*)&red[rb][2][jj][0];
            float4 p3 = *(const float4*)&red[rb][3][jj][0];
            float4 p4 = *(const float4*)&red[rb][4][jj][0];
            float4 p5 = *(const float4*)&red[rb][5][jj][0];
            float4 p6 = *(const float4*)&red[rb][6][jj][0];
            float4 p7 = *(const float4*)&red[rb][7][jj][0];
            float h0 = tanhf(((p0.x + p1.x) + (p2.x + p3.x)) +
                             ((p4.x + p5.x) + (p6.x + p7.x)) + xv0 + bhv);
            float h1 = tanhf(((p0.y + p1.y) + (p2.y + p3.y)) +
                             ((p4.y + p5.y) + (p6.y + p7.y)) + xv1 + bhv);
            float h2 = tanhf(((p0.z + p1.z) + (p2.z + p3.z)) +
                             ((p4.z + p5.z) + (p6.z + p7.z)) + xv2 + bhv);
            float h3 = tanhf(((p0.w + p1.w) + (p2.w + p3.w)) +
                             ((p4.w + p5.w) + (p6.w + p7.w)) + xv3 + bhv);

            int t_out = dir ? (TT - 1 - s) : s;
            size_t zb = (size_t)t_out * (2 * HH) + dir * HH + j;
            g_z[zb]                           = tf32r(h0);
            g_z[zb + (size_t)TT * 2 * HH]     = tf32r(h1);
            g_z[zb + (size_t)2 * TT * 2 * HH] = tf32r(h2);
            g_z[zb + (size_t)3 * TT * 2 * HH] = tf32r(h3);
            if (s == TT - 1) {
                size_t ob = YSIZE + (size_t)dir * (NB * HH) + j;
                out[ob]          = h0;
                out[ob + HH]     = h1;
                out[ob + 2 * HH] = h2;
                out[ob + 3 * HH] = h3;
            }

            if (s < TT - 1) {
                uint32_t off = (uint32_t)wb * (HH * NB * 4) + (uint32_t)j * 16;
                uint32_t mof = (uint32_t)wb * 8;
                uint32_t u0 = __float_as_uint(h0), u1 = __float_as_uint(h1);
                uint32_t u2 = __float_as_uint(h2), u3 = __float_as_uint(h3);
#pragma unroll
                for (int c = 0; c < CLU; ++c)
                    asm volatile(
                        "st.async.shared::cluster.mbarrier::complete_tx::bytes.v4.b32 "
                        "[%0], {%1,%2,%3,%4}, [%5];"
                        :: "r"(rh[c] + off), "r"(u0), "r"(u1), "r"(u2), "r"(u3),
                           "r"(rm[c] + mof) : "memory");
            }
        }
    }
}

// ---------------------------------------------------------------------------
// Kernel 3: tf32 mma.sync GEMM,  C = exp(z @ Wt^T + bias), row sums -> g_rowsum
// CTA tile 256x128x32, 512 threads (16 warps = 4m x 4n), 3-stage cp.async.
// ---------------------------------------------------------------------------
#define STAGE  49152
#define GSMEM  (3*STAGE + 1024)

__global__ __launch_bounds__(512, 1)
void gemm_kernel(const float* __restrict__ bias, float* __restrict__ C)
{
    extern __shared__ char dsm[];
    uint32_t smbase = (smem_u32(dsm) + 1023) & ~1023u;

    int tid  = threadIdx.x;
    int lane = tid & 31, w = tid >> 5;    // 16 warps
    int wm = w >> 2, wn = w & 3;          // 4m x 4n
    int m0 = blockIdx.x * 256, n0 = blockIdx.y * 128;

    // ---- loader constants: 4 A + 2 B float4 copies per thread per chunk ----
    // byte offsets into the source row block (row*4096 + c4*16), chunk adds 128B
    uint32_t sOff[6], gOff[6];
#pragma unroll
    for (int q = 0; q < 4; ++q) {
        int idx = q * 512 + tid;              // 0..2047
        int row = idx >> 3, c4 = idx & 7;
        sOff[q] = swz((uint32_t)(row * 128 + c4 * 16));
        gOff[q] = (uint32_t)(row * 4096 + c4 * 16);
    }
#pragma unroll
    for (int q = 4; q < 6; ++q) {
        int idx = (q - 4) * 512 + tid;        // 0..1023
        int row = idx >> 3, c4 = idx & 7;
        sOff[q] = 32768u + swz((uint32_t)(row * 128 + c4 * 16));
        gOff[q] = (uint32_t)(row * 4096 + c4 * 16);
    }
    const char* Abase = (const char*)(g_z  + (size_t)m0 * 1024);
    const char* Bbase = (const char*)(g_Wt + (size_t)n0 * 1024);

    // ---- fragment address constants ----
    int r = lane & 7, g = lane >> 3;
    uint32_t maskv = (uint32_t)r << 4;
    uint32_t hA = (uint32_t)(g >> 1) << 4;
    uint32_t hB = (uint32_t)(g & 1) << 4;
    uint32_t rowA[4], rowB[2];
#pragma unroll
    for (int mf = 0; mf < 4; ++mf)
        rowA[mf] = (uint32_t)((wm * 64 + mf * 16 + (g & 1) * 8 + r) * 128);
#pragma unroll
    for (int nf2 = 0; nf2 < 2; ++nf2)
        rowB[nf2] = 32768u + (uint32_t)((wn * 32 + nf2 * 16 + (g >> 1) * 8 + r) * 128);

    float acc[4][4][4];
#pragma unroll
    for (int i = 0; i < 4; ++i)
#pragma unroll
        for (int jx = 0; jx < 4; ++jx)
#pragma unroll
            for (int e = 0; e < 4; ++e) acc[i][jx][e] = 0.f;

    // ---- prologue: chunks 0,1 ----
#pragma unroll
    for (int q = 0; q < 4; ++q) cp16(smbase + sOff[q], Abase + gOff[q]);
#pragma unroll
    for (int q = 4; q < 6; ++q) cp16(smbase + sOff[q], Bbase + gOff[q]);
    cp_commit();
#pragma unroll
    for (int q = 0; q < 4; ++q) cp16(smbase + STAGE + sOff[q], Abase + gOff[q] + 128);
#pragma unroll
    for (int q = 4; q < 6; ++q) cp16(smbase + STAGE + sOff[q], Bbase + gOff[q] + 128);
    cp_commit();

    for (int c = 0; c < 32; ++c) {
        if (c < 31) cp_wait1(); else cp_wait0();
        __syncthreads();

        if (c + 2 < 32) {
            uint32_t sb = smbase + (uint32_t)((c + 2) % 3) * STAGE;
            uint32_t ko = (uint32_t)(c + 2) * 128;
#pragma unroll
            for (int q = 0; q < 4; ++q) cp16(sb + sOff[q], Abase + gOff[q] + ko);
#pragma unroll
            for (int q = 4; q < 6; ++q) cp16(sb + sOff[q], Bbase + gOff[q] + ko);
            cp_commit();
        }

        uint32_t sb = smbase + (uint32_t)(c % 3) * STAGE;
#pragma unroll
        for (int kk = 0; kk < 4; ++kk) {
            uint32_t kof = (uint32_t)kk << 5;
            uint32_t ua[4][4], ub[2][4];
#pragma unroll
            for (int mf = 0; mf < 4; ++mf)
                ldsm4(sb + rowA[mf] + ((kof + hA) ^ maskv),
                      ua[mf][0], ua[mf][1], ua[mf][2], ua[mf][3]);
#pragma unroll
            for (int nf2 = 0; nf2 < 2; ++nf2)
                ldsm4(sb + rowB[nf2] + ((kof + hB) ^ maskv),
                      ub[nf2][0], ub[nf2][1], ub[nf2][2], ub[nf2][3]);
#pragma unroll
            for (int mf = 0; mf < 4; ++mf)
#pragma unroll
                for (int nf = 0; nf < 4; ++nf)
                    mma8(acc[mf][nf], ua[mf],
                         ub[nf >> 1][(nf & 1) * 2], ub[nf >> 1][(nf & 1) * 2 + 1]);
        }
        __syncthreads();
    }

    // ---- epilogue: exp(logit+bias), store, quad-reduced row sums -> atomic ----
    float bb0[4], bb1[4];
#pragma unroll
    for (int nf = 0; nf < 4; ++nf) {
        int gcol = n0 + wn * 32 + nf * 8 + 2 * (lane & 3);
        bb0[nf] = bias[gcol];
        bb1[nf] = bias[gcol + 1];
    }
#pragma unroll
    for (int mf = 0; mf < 4; ++mf) {
        int grow = m0 + wm * 64 + mf * 16 + (lane >> 2);
        float rsA = 0.f, rsB = 0.f;
#pragma unroll
        for (int nf = 0; nf < 4; ++nf) {
            int gcol = n0 + wn * 32 + nf * 8 + 2 * (lane & 3);
            float e0 = __expf(acc[mf][nf][0] + bb0[nf]);
            float e1 = __expf(acc[mf][nf][1] + bb1[nf]);
            float e2 = __expf(acc[mf][nf][2] + bb0[nf]);
            float e3 = __expf(acc[mf][nf][3] + bb1[nf]);
            *(float2*)(C + (size_t)grow * VV + gcol)       = make_float2(e0, e1);
            *(float2*)(C + (size_t)(grow + 8) * VV + gcol) = make_float2(e2, e3);
            rsA += e0 + e1;
            rsB += e2 + e3;
        }
        rsA += __shfl_xor_sync(0xffffffffu, rsA, 1);
        rsA += __shfl_xor_sync(0xffffffffu, rsA, 2);
        rsB += __shfl_xor_sync(0xffffffffu, rsB, 1);
        rsB += __shfl_xor_sync(0xffffffffu, rsB, 2);
        if ((lane & 3) == 0) {
            atomicAdd(&g_rowsum[grow], rsA);
            atomicAdd(&g_rowsum[grow + 8], rsB);
        }
    }
}

// ---------------------------------------------------------------------------
// Kernel 4: normalize pass  C[row][:] *= 1/g_rowsum[row]
// ---------------------------------------------------------------------------
__global__ __launch_bounds__(256, 4)
void norm_kernel(float* __restrict__ C)
{
    float inv = 1.0f / g_rowsum[blockIdx.x];
    float4* x = (float4*)(C + blockIdx.x * (size_t)VV);
    for (int i = threadIdx.x; i < VV / 4; i += 256) {
        float4 v = x[i];
        v.x *= inv; v.y *= inv; v.z *= inv; v.w *= inv;
        x[i] = v;
    }
}

// ---------------------------------------------------------------------------
extern "C" void kernel_launch(void* const* d_in, const int* in_sizes, int n_in,
                              void* d_out, int out_size)
{
    const int*   x       = (const int*)  d_in[0];
    const float* embed_f = (const float*)d_in[1];
    const float* Wh_f    = (const float*)d_in[2];
    const float* bh_f    = (const float*)d_in[3];
    const float* embed_b = (const float*)d_in[4];
    const float* Wh_b    = (const float*)d_in[5];
    const float* bh_b    = (const float*)d_in[6];
    const float* Wout    = (const float*)d_in[7];
    const float* bout    = (const float*)d_in[8];
    float* out = (float*)d_out;

    cudaFuncSetAttribute(gemm_kernel, cudaFuncAttributeMaxDynamicSharedMemorySize,
                         GSMEM);
    cudaFuncSetAttribute(rnn_kernel,
                         cudaFuncAttributeNonPortableClusterSizeAllowed, 1);

    gather_kernel<<<2 * TT * NB, 128>>>(x, embed_f, embed_b);
    transpose_kernel<<<dim3(VV / 32, 1024 / 32), 256>>>(Wout);
    zero_kernel<<<MROWS / 1024, 1024>>>();
    rnn_kernel<<<2 * CLU, 256>>>(Wh_f, Wh_b, bh_f, bh_b, out);
    gemm_kernel<<<dim3(MROWS / 256, VV / 128), 512, GSMEM>>>(bout, out);
    norm_kernel<<<MROWS, 256>>>(out);
}

// round 14
// speedup vs baseline: 1.0454x; 1.0454x over previous
#include <cuda_runtime.h>
#include <cuda_bf16.h>
#include <cstdint>

// Problem constants
#define NB   4
#define TT   1024
#define VV   32000
#define HH   512
#define MROWS (NB*TT)            // 4096
#define YSIZE ((size_t)MROWS*VV) // 131072000

#define CLU  16                  // cluster size per direction
#define JPC  (HH/CLU)            // 32 j-columns per CTA
#define KSL  8                   // K-slices per CTA
#define ISL  (HH/KSL)            // 64 i-elements per slice

// Scratch (allocation-free rule -> __device__ globals)
__device__ float g_xh[2u*TT*NB*HH];       // [dir][s][n][j] 16 MB
__device__ float g_z[(size_t)MROWS*2*HH]; // [m][k] tf32-rounded A-matrix, 16 MB
__device__ float g_Wt[(size_t)VV*1024];   // Wout^T [n][k] tf32-rounded, 128 MB
__device__ float g_rowsum[MROWS];         // softmax denominators

// ---------------------------------------------------------------------------
// helpers
// ---------------------------------------------------------------------------
__device__ __forceinline__ unsigned smem_u32(const void* p)
{
    unsigned a;
    asm("{ .reg .u64 t; cvta.to.shared.u64 t, %1; cvt.u32.u64 %0, t; }"
        : "=r"(a) : "l"(p));
    return a;
}

__device__ __forceinline__ uint32_t swz(uint32_t o) { return o ^ ((o >> 3) & 0x70); }

__device__ __forceinline__ float tf32r(float f)      // round-to-nearest tf32
{
    uint32_t r;
    asm("cvt.rna.tf32.f32 %0, %1;" : "=r"(r) : "f"(f));
    return __uint_as_float(r);
}

__device__ __forceinline__ void cp16(uint32_t saddr, const void* gaddr)
{
    asm volatile("cp.async.cg.shared.global [%0], [%1], 16;"
                 :: "r"(saddr), "l"(gaddr) : "memory");
}
__device__ __forceinline__ void cp_commit()
{
    asm volatile("cp.async.commit_group;" ::: "memory");
}
__device__ __forceinline__ void cp_wait1()
{
    asm volatile("cp.async.wait_group 1;" ::: "memory");
}
__device__ __forceinline__ void cp_wait0()
{
    asm volatile("cp.async.wait_group 0;" ::: "memory");
}

__device__ __forceinline__ void ldsm4(uint32_t addr, uint32_t& r0, uint32_t& r1,
                                      uint32_t& r2, uint32_t& r3)
{
    asm volatile("ldmatrix.sync.aligned.m8n8.x4.shared.b16 {%0,%1,%2,%3}, [%4];"
                 : "=r"(r0), "=r"(r1), "=r"(r2), "=r"(r3) : "r"(addr));
}

__device__ __forceinline__ void mma8(float* d, const uint32_t* a,
                                     uint32_t b0, uint32_t b1)
{
    asm volatile("mma.sync.aligned.m16n8k8.row.col.f32.tf32.tf32.f32 "
                 "{%0,%1,%2,%3}, {%4,%5,%6,%7}, {%8,%9}, {%0,%1,%2,%3};"
                 : "+f"(d[0]), "+f"(d[1]), "+f"(d[2]), "+f"(d[3])
                 : "r"(a[0]), "r"(a[1]), "r"(a[2]), "r"(a[3]), "r"(b0), "r"(b1));
}

__device__ __forceinline__ void mbar_wait_cluster(uint32_t a, uint32_t ph)
{
    asm volatile("{\n\t.reg .pred P;\n\tWL%=:\n\t"
                 "mbarrier.try_wait.parity.acquire.cluster.shared::cta.b64 P, [%0], %1, 0x989680;\n\t"
                 "@!P bra WL%=;\n\t}"
                 :: "r"(a), "r"(ph) : "memory");
}

// ---------------------------------------------------------------------------
// Kernel 1: embedding gather (+ rowsum zeroing folded in)
// ---------------------------------------------------------------------------
__global__ __launch_bounds__(128)
void gather_kernel(const int* __restrict__ x,
                   const float* __restrict__ Ef,
                   const float* __restrict__ Eb)
{
    int b   = blockIdx.x;
    if (b < 32) g_rowsum[b * 128 + threadIdx.x] = 0.f;
    int dir = b >> 12;
    int s   = (b >> 2) & 1023;
    int n   = b & 3;
    int t   = dir ? (TT - 1 - s) : s;
    int tok = x[n * TT + t];
    const float4* src = (const float4*)((dir ? Eb : Ef) + (size_t)tok * HH);
    float4* dst = (float4*)(g_xh + ((size_t)(dir * TT + s) * NB + n) * HH);
    dst[threadIdx.x] = src[threadIdx.x];
}

// ---------------------------------------------------------------------------
// Kernel 1b: transpose Wout[k][n] -> g_Wt[n][k], tf32-rounded at write
// ---------------------------------------------------------------------------
__global__ __launch_bounds__(256)
void transpose_kernel(const float* __restrict__ Wout)
{
    __shared__ float t[32][33];
    int n0 = blockIdx.x * 32;
    int k0 = blockIdx.y * 32;
    int tx = threadIdx.x & 31, ty = threadIdx.x >> 5;
#pragma unroll
    for (int r = 0; r < 32; r += 8)
        t[ty + r][tx] = Wout[(size_t)(k0 + ty + r) * VV + n0 + tx];
    __syncthreads();
#pragma unroll
    for (int r = 0; r < 32; r += 8)
        g_Wt[(size_t)(n0 + ty + r) * 1024 + k0 + tx] = tf32r(t[tx][ty + r]);
}

// ---------------------------------------------------------------------------
// Kernel 2: bidirectional RNN scan, cluster-of-16 per direction.
// st.async + mbarrier complete_tx; broadcast FIRST in phase 2 (critical path),
// global stores after; broadcast target order staggered by cluster rank.
// ---------------------------------------------------------------------------
__global__ __cluster_dims__(CLU, 1, 1) __launch_bounds__(256, 1)
void rnn_kernel(const float* __restrict__ Wh_f, const float* __restrict__ Wh_b,
                const float* __restrict__ bh_f, const float* __restrict__ bh_b,
                float* __restrict__ out)
{
    __shared__ float    h_s[2][HH][NB];       // [buf][j][n], 16 KB
    __shared__ float    red[2][KSL][JPC][4];  // [buf][kslice][jj][n], 8 KB
    __shared__ uint64_t mbar[2];

    int tid = threadIdx.x;
    int jj  = tid & 31;
    int ks  = tid >> 5;            // 0..7
    unsigned crank;
    asm("mov.u32 %0, %%cluster_ctarank;" : "=r"(crank));
    int dir = blockIdx.x >> 4;
    int j   = (int)crank * JPC + jj;

    const float* Wh = dir ? Wh_b : Wh_f;
    const float* bh = dir ? bh_b : bh_f;

    // register-resident packed weight slice: {w,w} for Wh[ks*64+u][j]
    uint64_t wpk[ISL];
#pragma unroll
    for (int u = 0; u < ISL; ++u) {
        uint32_t wu = __float_as_uint(Wh[(size_t)(ks * ISL + u) * HH + j]);
        asm("mov.b64 %0, {%1, %1};" : "=l"(wpk[u]) : "r"(wu));
    }
    float bhv = bh[j];

    // init: zero h buffer 0, init + pre-arm both mbarriers
    for (int i = tid; i < HH * NB; i += 256) ((float*)h_s[0])[i] = 0.f;
    if (tid == 0) {
        uint32_t m0 = smem_u32(&mbar[0]), m1 = smem_u32(&mbar[1]);
        asm volatile("mbarrier.init.shared.b64 [%0], 1;" :: "r"(m0) : "memory");
        asm volatile("mbarrier.init.shared.b64 [%0], 1;" :: "r"(m1) : "memory");
        asm volatile("fence.mbarrier_init.release.cluster;" ::: "memory");
        asm volatile("mbarrier.arrive.expect_tx.shared.b64 _, [%0], %1;"
                     :: "r"(m0), "r"(8192u) : "memory");
        asm volatile("mbarrier.arrive.expect_tx.shared.b64 _, [%0], %1;"
                     :: "r"(m1), "r"(8192u) : "memory");
    }
    __syncthreads();
    asm volatile("barrier.cluster.arrive.aligned;" ::: "memory");
    asm volatile("barrier.cluster.wait.aligned;"   ::: "memory");

    // remote base addresses, staggered start per rank
    uint32_t hloc = smem_u32(&h_s[0][0][0]);
    uint32_t mloc = smem_u32(&mbar[0]);
    uint32_t rh[CLU], rm[CLU];
#pragma unroll
    for (int c = 0; c < CLU; ++c) {
        int cc = (int)((crank + c) & (CLU - 1));
        asm("mapa.shared::cluster.u32 %0, %1, %2;" : "=r"(rh[c]) : "r"(hloc), "r"(cc));
        asm("mapa.shared::cluster.u32 %0, %1, %2;" : "=r"(rm[c]) : "r"(mloc), "r"(cc));
    }

    const float* xh_base = g_xh + (size_t)dir * TT * NB * HH;
    uint32_t ph0 = 0, ph1 = 0;

    for (int s = 0; s < TT; ++s) {
        int rb = s & 1;        // h read buffer / red buffer
        int wb = rb ^ 1;       // h write buffer

        if (s > 0) {
            uint32_t mb = mloc + (uint32_t)rb * 8;
            mbar_wait_cluster(mb, rb ? ph1 : ph0);
            if (tid == 0)
                asm volatile("mbarrier.arrive.expect_tx.shared.b64 _, [%0], %1;"
                             :: "r"(mb), "r"(8192u) : "memory");
            if (rb) ph1 ^= 1; else ph0 ^= 1;
        }

        // prefetch xh for phase 2 (threads 0..31 only)
        float xv0 = 0.f, xv1 = 0.f, xv2 = 0.f, xv3 = 0.f;
        if (tid < JPC) {
            const float* xp = xh_base + (size_t)s * NB * HH + j;
            xv0 = xp[0]; xv1 = xp[HH]; xv2 = xp[2 * HH]; xv3 = xp[3 * HH];
        }

        // phase 1: packed partial dot for 4 batch rows over 64 K-elements
        uint64_t a01 = 0ull, a23 = 0ull;
        uint32_t hb = hloc + (uint32_t)rb * (HH * NB * 4) + (uint32_t)(ks * ISL) * 16;
#pragma unroll
        for (int u = 0; u < ISL; ++u) {
            uint64_t h01, h23;
            asm("ld.shared.v2.b64 {%0,%1}, [%2];"
                : "=l"(h01), "=l"(h23) : "r"(hb + u * 16));
            asm("fma.rn.f32x2 %0, %1, %2, %0;" : "+l"(a01) : "l"(h01), "l"(wpk[u]));
            asm("fma.rn.f32x2 %0, %1, %2, %0;" : "+l"(a23) : "l"(h23), "l"(wpk[u]));
        }
        {
            uint32_t rw = smem_u32(&red[rb][ks][jj][0]);
            asm volatile("st.shared.v2.b64 [%0], {%1,%2};"
                         :: "r"(rw), "l"(a01), "l"(a23) : "memory");
        }
        __syncthreads();

        // phase 2: thread jj (tid<32) handles column j, all 4 batches
        if (tid < JPC) {
            float4 p0 = *(const float4*)&red[rb][0][jj][0];
            float4 p1 = *(const float4*)&red[rb][1][jj][0];
            float4 p2 = *(const float4*)&red[rb][2][jj][0];
            float4 p3 = *(const float4*)&red[rb][3][jj][0];
            float4 p4 = *(const float4*)&red[rb][4][jj][0];
            float4 p5 = *(const float4*)&red[rb][5][jj][0];
            float4 p6 = *(const float4*)&red[rb][6][jj][0];
            float4 p7 = *(const float4*)&red[rb][7][jj][0];
            float h0 = tanhf(((p0.x + p1.x) + (p2.x + p3.x)) +
                             ((p4.x + p5.x) + (p6.x + p7.x)) + xv0 + bhv);
            float h1 = tanhf(((p0.y + p1.y) + (p2.y + p3.y)) +
                             ((p4.y + p5.y) + (p6.y + p7.y)) + xv1 + bhv);
            float h2 = tanhf(((p0.z + p1.z) + (p2.z + p3.z)) +
                             ((p4.z + p5.z) + (p6.z + p7.z)) + xv2 + bhv);
            float h3 = tanhf(((p0.w + p1.w) + (p2.w + p3.w)) +
                             ((p4.w + p5.w) + (p6.w + p7.w)) + xv3 + bhv);

            // broadcast FIRST: the whole cluster waits on these bytes
            if (s < TT - 1) {
                uint32_t off = (uint32_t)wb * (HH * NB * 4) + (uint32_t)j * 16;
                uint32_t mof = (uint32_t)wb * 8;
                uint32_t u0 = __float_as_uint(h0), u1 = __float_as_uint(h1);
                uint32_t u2 = __float_as_uint(h2), u3 = __float_as_uint(h3);
#pragma unroll
                for (int c = 0; c < CLU; ++c)
                    asm volatile(
                        "st.async.shared::cluster.mbarrier::complete_tx::bytes.v4.b32 "
                        "[%0], {%1,%2,%3,%4}, [%5];"
                        :: "r"(rh[c] + off), "r"(u0), "r"(u1), "r"(u2), "r"(u3),
                           "r"(rm[c] + mof) : "memory");
            }

            // global stores off the critical path
            int t_out = dir ? (TT - 1 - s) : s;
            size_t zb = (size_t)t_out * (2 * HH) + dir * HH + j;
            g_z[zb]                           = tf32r(h0);
            g_z[zb + (size_t)TT * 2 * HH]     = tf32r(h1);
            g_z[zb + (size_t)2 * TT * 2 * HH] = tf32r(h2);
            g_z[zb + (size_t)3 * TT * 2 * HH] = tf32r(h3);
            if (s == TT - 1) {
                size_t ob = YSIZE + (size_t)dir * (NB * HH) + j;
                out[ob]          = h0;
                out[ob + HH]     = h1;
                out[ob + 2 * HH] = h2;
                out[ob + 3 * HH] = h3;
            }
        }
    }
}

// ---------------------------------------------------------------------------
// Kernel 3: tf32 mma.sync GEMM,  C = exp(z @ Wt^T + bias), row sums -> g_rowsum
// CTA tile 128x128x32, 256 threads (2m x 4n warps), 3-stage cp.async,
// 2 CTAs/SM co-residency (GSMEM = 99328).
// ---------------------------------------------------------------------------
#define GSMEM (3*32768 + 1024)

__global__ __launch_bounds__(256)
void gemm_kernel(const float* __restrict__ bias, float* __restrict__ C)
{
    extern __shared__ char dsm[];
    uint32_t smbase = (smem_u32(dsm) + 1023) & ~1023u;

    int tid  = threadIdx.x;
    int lane = tid & 31, w = tid >> 5;
    int wm = w >> 2, wn = w & 3;
    int m0 = blockIdx.x * 128, n0 = blockIdx.y * 128;

    uint32_t sOff[8];
    const float* gP[8];
#pragma unroll
    for (int q = 0; q < 4; ++q) {
        int idx = q * 256 + tid;
        int row = idx >> 3, c4 = idx & 7;
        sOff[q]     = swz((uint32_t)(row * 128 + c4 * 16));
        sOff[q + 4] = 16384u + sOff[q];
        gP[q]     = g_z  + (size_t)(m0 + row) * 1024 + c4 * 4;
        gP[q + 4] = g_Wt + (size_t)(n0 + row) * 1024 + c4 * 4;
    }

    int r = lane & 7, g = lane >> 3;
    uint32_t maskv = (uint32_t)r << 4;
    uint32_t hA = (uint32_t)(g >> 1) << 4;
    uint32_t hB = (uint32_t)(g & 1) << 4;
    uint32_t rowA[4], rowB[2];
#pragma unroll
    for (int mf = 0; mf < 4; ++mf)
        rowA[mf] = (uint32_t)((wm * 64 + mf * 16 + (g & 1) * 8 + r) * 128);
#pragma unroll
    for (int nf2 = 0; nf2 < 2; ++nf2)
        rowB[nf2] = 16384u + (uint32_t)((wn * 32 + nf2 * 16 + (g >> 1) * 8 + r) * 128);

    float acc[4][4][4];
#pragma unroll
    for (int i = 0; i < 4; ++i)
#pragma unroll
        for (int jx = 0; jx < 4; ++jx)
#pragma unroll
            for (int e = 0; e < 4; ++e) acc[i][jx][e] = 0.f;

#pragma unroll
    for (int q = 0; q < 8; ++q) cp16(smbase + sOff[q], gP[q]);
    cp_commit();
#pragma unroll
    for (int q = 0; q < 8; ++q) cp16(smbase + 32768 + sOff[q], gP[q] + 32);
    cp_commit();

    for (int c = 0; c < 32; ++c) {
        if (c < 31) cp_wait1(); else cp_wait0();
        __syncthreads();

        if (c + 2 < 32) {
            uint32_t sb = smbase + (uint32_t)((c + 2) % 3) * 32768;
            const int ko = (c + 2) * 32;
#pragma unroll
            for (int q = 0; q < 8; ++q) cp16(sb + sOff[q], gP[q] + ko);
            cp_commit();
        }

        uint32_t sb = smbase + (uint32_t)(c % 3) * 32768;
#pragma unroll
        for (int kk = 0; kk < 4; ++kk) {
            uint32_t kof = (uint32_t)kk << 5;
            uint32_t ua[4][4], ub[2][4];
#pragma unroll
            for (int mf = 0; mf < 4; ++mf)
                ldsm4(sb + rowA[mf] + ((kof + hA) ^ maskv),
                      ua[mf][0], ua[mf][1], ua[mf][2], ua[mf][3]);
#pragma unroll
            for (int nf2 = 0; nf2 < 2; ++nf2)
                ldsm4(sb + rowB[nf2] + ((kof + hB) ^ maskv),
                      ub[nf2][0], ub[nf2][1], ub[nf2][2], ub[nf2][3]);
#pragma unroll
            for (int mf = 0; mf < 4; ++mf)
#pragma unroll
                for (int nf = 0; nf < 4; ++nf)
                    mma8(acc[mf][nf], ua[mf],
                         ub[nf >> 1][(nf & 1) * 2], ub[nf >> 1][(nf & 1) * 2 + 1]);
        }
        __syncthreads();
    }

    // epilogue: exp(logit+bias), store, quad-reduced row sums -> atomic
    float bb0[4], bb1[4];
#pragma unroll
    for (int nf = 0; nf < 4; ++nf) {
        int gcol = n0 + wn * 32 + nf * 8 + 2 * (lane & 3);
        bb0[nf] = bias[gcol];
        bb1[nf] = bias[gcol + 1];
    }
#pragma unroll
    for (int mf = 0; mf < 4; ++mf) {
        int grow = m0 + wm * 64 + mf * 16 + (lane >> 2);
        float rsA = 0.f, rsB = 0.f;
#pragma unroll
        for (int nf = 0; nf < 4; ++nf) {
            int gcol = n0 + wn * 32 + nf * 8 + 2 * (lane & 3);
            float e0 = __expf(acc[mf][nf][0] + bb0[nf]);
            float e1 = __expf(acc[mf][nf][1] + bb1[nf]);
            float e2 = __expf(acc[mf][nf][2] + bb0[nf]);
            float e3 = __expf(acc[mf][nf][3] + bb1[nf]);
            *(float2*)(C + (size_t)grow * VV + gcol)       = make_float2(e0, e1);
            *(float2*)(C + (size_t)(grow + 8) * VV + gcol) = make_float2(e2, e3);
            rsA += e0 + e1;
            rsB += e2 + e3;
        }
        rsA += __shfl_xor_sync(0xffffffffu, rsA, 1);
        rsA += __shfl_xor_sync(0xffffffffu, rsA, 2);
        rsB += __shfl_xor_sync(0xffffffffu, rsB, 1);
        rsB += __shfl_xor_sync(0xffffffffu, rsB, 2);
        if ((lane & 3) == 0) {
            atomicAdd(&g_rowsum[grow], rsA);
            atomicAdd(&g_rowsum[grow + 8], rsB);
        }
    }
}

// ---------------------------------------------------------------------------
// Kernel 4: normalize pass  C[row][:] *= 1/g_rowsum[row]
// ---------------------------------------------------------------------------
__global__ __launch_bounds__(256, 4)
void norm_kernel(float* __restrict__ C)
{
    float inv = 1.0f / g_rowsum[blockIdx.x];
    float4* x = (float4*)(C + blockIdx.x * (size_t)VV);
    for (int i = threadIdx.x; i < VV / 4; i += 256) {
        float4 v = x[i];
        v.x *= inv; v.y *= inv; v.z *= inv; v.w *= inv;
        x[i] = v;
    }
}

// ---------------------------------------------------------------------------
extern "C" void kernel_launch(void* const* d_in, const int* in_sizes, int n_in,
                              void* d_out, int out_size)
{
    const int*   x       = (const int*)  d_in[0];
    const float* embed_f = (const float*)d_in[1];
    const float* Wh_f    = (const float*)d_in[2];
    const float* bh_f    = (const float*)d_in[3];
    const float* embed_b = (const float*)d_in[4];
    const float* Wh_b    = (const float*)d_in[5];
    const float* bh_b    = (const float*)d_in[6];
    const float* Wout    = (const float*)d_in[7];
    const float* bout    = (const float*)d_in[8];
    float* out = (float*)d_out;

    cudaFuncSetAttribute(gemm_kernel, cudaFuncAttributeMaxDynamicSharedMemorySize,
                         GSMEM);
    cudaFuncSetAttribute(rnn_kernel,
                         cudaFuncAttributeNonPortableClusterSizeAllowed, 1);

    gather_kernel<<<2 * TT * NB, 128>>>(x, embed_f, embed_b);
    transpose_kernel<<<dim3(VV / 32, 1024 / 32), 256>>>(Wout);
    rnn_kernel<<<2 * CLU, 256>>>(Wh_f, Wh_b, bh_f, bh_b, out);
    gemm_kernel<<<dim3(MROWS / 128, VV / 128), 256, GSMEM>>>(bout, out);
    norm_kernel<<<MROWS, 256>>>(out);
}

// round 15
// speedup vs baseline: 1.3671x; 1.3077x over previous
#include <cuda_runtime.h>
#include <cuda_bf16.h>
#include <cstdint>

// Problem constants
#define NB   4
#define TT   1024
#define VV   32000
#define HH   512
#define MROWS (NB*TT)            // 4096
#define YSIZE ((size_t)MROWS*VV) // 131072000

#define CLU  16                  // cluster size per direction
#define JPC  (HH/CLU)            // 32 j-columns per CTA
#define KSL  8                   // K-slices per CTA
#define ISL  (HH/KSL)            // 64 i-elements per slice

// Scratch (allocation-free rule -> __device__ globals)
__device__ float         g_xh[2u*TT*NB*HH];        // [dir][s][n][j] 16 MB
__device__ __nv_bfloat16 g_z[(size_t)MROWS*2*HH];  // [m][k] bf16 A-matrix, 8 MB
__device__ __nv_bfloat16 g_Wt[(size_t)VV*1024];    // Wout^T [n][k] bf16, 64 MB
__device__ float         g_rowsum[MROWS];          // softmax denominators

// ---------------------------------------------------------------------------
// helpers
// ---------------------------------------------------------------------------
__device__ __forceinline__ unsigned smem_u32(const void* p)
{
    unsigned a;
    asm("{ .reg .u64 t; cvta.to.shared.u64 t, %1; cvt.u32.u64 %0, t; }"
        : "=r"(a) : "l"(p));
    return a;
}

__device__ __forceinline__ uint32_t swz(uint32_t o) { return o ^ ((o >> 3) & 0x70); }

__device__ __forceinline__ void cp16(uint32_t saddr, const void* gaddr)
{
    asm volatile("cp.async.cg.shared.global [%0], [%1], 16;"
                 :: "r"(saddr), "l"(gaddr) : "memory");
}
__device__ __forceinline__ void cp_commit()
{
    asm volatile("cp.async.commit_group;" ::: "memory");
}
__device__ __forceinline__ void cp_wait1()
{
    asm volatile("cp.async.wait_group 1;" ::: "memory");
}
__device__ __forceinline__ void cp_wait0()
{
    asm volatile("cp.async.wait_group 0;" ::: "memory");
}

__device__ __forceinline__ void ldsm4(uint32_t addr, uint32_t& r0, uint32_t& r1,
                                      uint32_t& r2, uint32_t& r3)
{
    asm volatile("ldmatrix.sync.aligned.m8n8.x4.shared.b16 {%0,%1,%2,%3}, [%4];"
                 : "=r"(r0), "=r"(r1), "=r"(r2), "=r"(r3) : "r"(addr));
}

// bf16 mma: m16n8k16, fp32 accumulate
__device__ __forceinline__ void mma16(float* d, const uint32_t* a,
                                      uint32_t b0, uint32_t b1)
{
    asm volatile("mma.sync.aligned.m16n8k16.row.col.f32.bf16.bf16.f32 "
                 "{%0,%1,%2,%3}, {%4,%5,%6,%7}, {%8,%9}, {%0,%1,%2,%3};"
                 : "+f"(d[0]), "+f"(d[1]), "+f"(d[2]), "+f"(d[3])
                 : "r"(a[0]), "r"(a[1]), "r"(a[2]), "r"(a[3]), "r"(b0), "r"(b1));
}

__device__ __forceinline__ void mbar_wait_cluster(uint32_t a, uint32_t ph)
{
    asm volatile("{\n\t.reg .pred P;\n\tWL%=:\n\t"
                 "mbarrier.try_wait.parity.acquire.cluster.shared::cta.b64 P, [%0], %1, 0x989680;\n\t"
                 "@!P bra WL%=;\n\t}"
                 :: "r"(a), "r"(ph) : "memory");
}

// ---------------------------------------------------------------------------
// Kernel 1: embedding gather (+ rowsum zeroing folded in)
// ---------------------------------------------------------------------------
__global__ __launch_bounds__(128)
void gather_kernel(const int* __restrict__ x,
                   const float* __restrict__ Ef,
                   const float* __restrict__ Eb)
{
    int b   = blockIdx.x;
    if (b < 32) g_rowsum[b * 128 + threadIdx.x] = 0.f;
    int dir = b >> 12;
    int s   = (b >> 2) & 1023;
    int n   = b & 3;
    int t   = dir ? (TT - 1 - s) : s;
    int tok = x[n * TT + t];
    const float4* src = (const float4*)((dir ? Eb : Ef) + (size_t)tok * HH);
    float4* dst = (float4*)(g_xh + ((size_t)(dir * TT + s) * NB + n) * HH);
    dst[threadIdx.x] = src[threadIdx.x];
}

// ---------------------------------------------------------------------------
// Kernel 1b: transpose Wout[k][n] -> g_Wt[n][k], bf16-rounded at write
// ---------------------------------------------------------------------------
__global__ __launch_bounds__(256)
void transpose_kernel(const float* __restrict__ Wout)
{
    __shared__ float t[32][33];
    int n0 = blockIdx.x * 32;
    int k0 = blockIdx.y * 32;
    int tx = threadIdx.x & 31, ty = threadIdx.x >> 5;
#pragma unroll
    for (int r = 0; r < 32; r += 8)
        t[ty + r][tx] = Wout[(size_t)(k0 + ty + r) * VV + n0 + tx];
    __syncthreads();
#pragma unroll
    for (int r = 0; r < 32; r += 8)
        g_Wt[(size_t)(n0 + ty + r) * 1024 + k0 + tx] = __float2bfloat16(t[tx][ty + r]);
}

// ---------------------------------------------------------------------------
// Kernel 2: bidirectional RNN scan, cluster-of-16 per direction.
// st.async + mbarrier complete_tx; broadcast first in phase 2 (critical path),
// global stores after; broadcast target order staggered by cluster rank.
// ---------------------------------------------------------------------------
__global__ __cluster_dims__(CLU, 1, 1) __launch_bounds__(256, 1)
void rnn_kernel(const float* __restrict__ Wh_f, const float* __restrict__ Wh_b,
                const float* __restrict__ bh_f, const float* __restrict__ bh_b,
                float* __restrict__ out)
{
    __shared__ float    h_s[2][HH][NB];       // [buf][j][n], 16 KB
    __shared__ float    red[2][KSL][JPC][4];  // [buf][kslice][jj][n], 8 KB
    __shared__ uint64_t mbar[2];

    int tid = threadIdx.x;
    int jj  = tid & 31;
    int ks  = tid >> 5;            // 0..7
    unsigned crank;
    asm("mov.u32 %0, %%cluster_ctarank;" : "=r"(crank));
    int dir = blockIdx.x >> 4;
    int j   = (int)crank * JPC + jj;

    const float* Wh = dir ? Wh_b : Wh_f;
    const float* bh = dir ? bh_b : bh_f;

    // register-resident packed weight slice: {w,w} for Wh[ks*64+u][j]
    uint64_t wpk[ISL];
#pragma unroll
    for (int u = 0; u < ISL; ++u) {
        uint32_t wu = __float_as_uint(Wh[(size_t)(ks * ISL + u) * HH + j]);
        asm("mov.b64 %0, {%1, %1};" : "=l"(wpk[u]) : "r"(wu));
    }
    float bhv = bh[j];

    // init: zero h buffer 0, init + pre-arm both mbarriers
    for (int i = tid; i < HH * NB; i += 256) ((float*)h_s[0])[i] = 0.f;
    if (tid == 0) {
        uint32_t m0 = smem_u32(&mbar[0]), m1 = smem_u32(&mbar[1]);
        asm volatile("mbarrier.init.shared.b64 [%0], 1;" :: "r"(m0) : "memory");
        asm volatile("mbarrier.init.shared.b64 [%0], 1;" :: "r"(m1) : "memory");
        asm volatile("fence.mbarrier_init.release.cluster;" ::: "memory");
        asm volatile("mbarrier.arrive.expect_tx.shared.b64 _, [%0], %1;"
                     :: "r"(m0), "r"(8192u) : "memory");
        asm volatile("mbarrier.arrive.expect_tx.shared.b64 _, [%0], %1;"
                     :: "r"(m1), "r"(8192u) : "memory");
    }
    __syncthreads();
    asm volatile("barrier.cluster.arrive.aligned;" ::: "memory");
    asm volatile("barrier.cluster.wait.aligned;"   ::: "memory");

    // remote base addresses, staggered start per rank
    uint32_t hloc = smem_u32(&h_s[0][0][0]);
    uint32_t mloc = smem_u32(&mbar[0]);
    uint32_t rh[CLU], rm[CLU];
#pragma unroll
    for (int c = 0; c < CLU; ++c) {
        int cc = (int)((crank + c) & (CLU - 1));
        asm("mapa.shared::cluster.u32 %0, %1, %2;" : "=r"(rh[c]) : "r"(hloc), "r"(cc));
        asm("mapa.shared::cluster.u32 %0, %1, %2;" : "=r"(rm[c]) : "r"(mloc), "r"(cc));
    }

    const float* xh_base = g_xh + (size_t)dir * TT * NB * HH;
    uint32_t ph0 = 0, ph1 = 0;

    for (int s = 0; s < TT; ++s) {
        int rb = s & 1;        // h read buffer / red buffer
        int wb = rb ^ 1;       // h write buffer

        if (s > 0) {
            uint32_t mb = mloc + (uint32_t)rb * 8;
            mbar_wait_cluster(mb, rb ? ph1 : ph0);
            if (tid == 0)
                asm volatile("mbarrier.arrive.expect_tx.shared.b64 _, [%0], %1;"
                             :: "r"(mb), "r"(8192u) : "memory");
            if (rb) ph1 ^= 1; else ph0 ^= 1;
        }

        // prefetch xh for phase 2 (threads 0..31 only)
        float xv0 = 0.f, xv1 = 0.f, xv2 = 0.f, xv3 = 0.f;
        if (tid < JPC) {
            const float* xp = xh_base + (size_t)s * NB * HH + j;
            xv0 = xp[0]; xv1 = xp[HH]; xv2 = xp[2 * HH]; xv3 = xp[3 * HH];
        }

        // phase 1: packed partial dot for 4 batch rows over 64 K-elements
        uint64_t a01 = 0ull, a23 = 0ull;
        uint32_t hb = hloc + (uint32_t)rb * (HH * NB * 4) + (uint32_t)(ks * ISL) * 16;
#pragma unroll
        for (int u = 0; u < ISL; ++u) {
            uint64_t h01, h23;
            asm("ld.shared.v2.b64 {%0,%1}, [%2];"
                : "=l"(h01), "=l"(h23) : "r"(hb + u * 16));
            asm("fma.rn.f32x2 %0, %1, %2, %0;" : "+l"(a01) : "l"(h01), "l"(wpk[u]));
            asm("fma.rn.f32x2 %0, %1, %2, %0;" : "+l"(a23) : "l"(h23), "l"(wpk[u]));
        }
        {
            uint32_t rw = smem_u32(&red[rb][ks][jj][0]);
            asm volatile("st.shared.v2.b64 [%0], {%1,%2};"
                         :: "r"(rw), "l"(a01), "l"(a23) : "memory");
        }
        __syncthreads();

        // phase 2: thread jj (tid<32) handles column j, all 4 batches
        if (tid < JPC) {
            float4 p0 = *(const float4*)&red[rb][0][jj][0];
            float4 p1 = *(const float4*)&red[rb][1][jj][0];
            float4 p2 = *(const float4*)&red[rb][2][jj][0];
            float4 p3 = *(const float4*)&red[rb][3][jj][0];
            float4 p4 = *(const float4*)&red[rb][4][jj][0];
            float4 p5 = *(const float4*)&red[rb][5][jj][0];
            float4 p6 = *(const float4*)&red[rb][6][jj][0];
            float4 p7 = *(const float4*)&red[rb][7][jj][0];
            float h0 = tanhf(((p0.x + p1.x) + (p2.x + p3.x)) +
                             ((p4.x + p5.x) + (p6.x + p7.x)) + xv0 + bhv);
            float h1 = tanhf(((p0.y + p1.y) + (p2.y + p3.y)) +
                             ((p4.y + p5.y) + (p6.y + p7.y)) + xv1 + bhv);
            float h2 = tanhf(((p0.z + p1.z) + (p2.z + p3.z)) +
                             ((p4.z + p5.z) + (p6.z + p7.z)) + xv2 + bhv);
            float h3 = tanhf(((p0.w + p1.w) + (p2.w + p3.w)) +
                             ((p4.w + p5.w) + (p6.w + p7.w)) + xv3 + bhv);

            // broadcast FIRST: the whole cluster waits on these bytes
            if (s < TT - 1) {
                uint32_t off = (uint32_t)wb * (HH * NB * 4) + (uint32_t)j * 16;
                uint32_t mof = (uint32_t)wb * 8;
                uint32_t u0 = __float_as_uint(h0), u1 = __float_as_uint(h1);
                uint32_t u2 = __float_as_uint(h2), u3 = __float_as_uint(h3);
#pragma unroll
                for (int c = 0; c < CLU; ++c)
                    asm volatile(
                        "st.async.shared::cluster.mbarrier::complete_tx::bytes.v4.b32 "
                        "[%0], {%1,%2,%3,%4}, [%5];"
                        :: "r"(rh[c] + off), "r"(u0), "r"(u1), "r"(u2), "r"(u3),
                           "r"(rm[c] + mof) : "memory");
            }

            // global stores off the critical path (bf16 for the GEMM A-matrix)
            int t_out = dir ? (TT - 1 - s) : s;
            size_t zb = (size_t)t_out * (2 * HH) + dir * HH + j;
            g_z[zb]                           = __float2bfloat16(h0);
            g_z[zb + (size_t)TT * 2 * HH]     = __float2bfloat16(h1);
            g_z[zb + (size_t)2 * TT * 2 * HH] = __float2bfloat16(h2);
            g_z[zb + (size_t)3 * TT * 2 * HH] = __float2bfloat16(h3);
            if (s == TT - 1) {
                size_t ob = YSIZE + (size_t)dir * (NB * HH) + j;
                out[ob]          = h0;
                out[ob + HH]     = h1;
                out[ob + 2 * HH] = h2;
                out[ob + 3 * HH] = h3;
            }
        }
    }
}

// ---------------------------------------------------------------------------
// Kernel 3: bf16 mma.sync GEMM,  C = exp(z @ Wt^T + bias), row sums -> g_rowsum
// CTA tile 128x128, K chunk 64 (128B bf16 rows), 16 chunks, 3-stage cp.async,
// 2 CTAs/SM co-residency (GSMEM = 99328). Fragment addressing identical to the
// tf32 version: each 16B unit now holds 8 bf16 (K=8) instead of 4 f32 (K=4).
// ---------------------------------------------------------------------------
#define GSMEM (3*32768 + 1024)

__global__ __launch_bounds__(256)
void gemm_kernel(const float* __restrict__ bias, float* __restrict__ C)
{
    extern __shared__ char dsm[];
    uint32_t smbase = (smem_u32(dsm) + 1023) & ~1023u;

    int tid  = threadIdx.x;
    int lane = tid & 31, w = tid >> 5;
    int wm = w >> 2, wn = w & 3;
    int m0 = blockIdx.x * 128, n0 = blockIdx.y * 128;

    // loader: 4 A + 4 B 16B copies per thread per chunk (32KB/chunk)
    uint32_t sOff[8];
    const char* gP[8];
#pragma unroll
    for (int q = 0; q < 4; ++q) {
        int idx = q * 256 + tid;
        int row = idx >> 3, c4 = idx & 7;
        sOff[q]     = swz((uint32_t)(row * 128 + c4 * 16));
        sOff[q + 4] = 16384u + sOff[q];
        gP[q]     = (const char*)g_z  + (size_t)(m0 + row) * 2048 + c4 * 16;
        gP[q + 4] = (const char*)g_Wt + (size_t)(n0 + row) * 2048 + c4 * 16;
    }

    int r = lane & 7, g = lane >> 3;
    uint32_t maskv = (uint32_t)r << 4;
    uint32_t hA = (uint32_t)(g >> 1) << 4;
    uint32_t hB = (uint32_t)(g & 1) << 4;
    uint32_t rowA[4], rowB[2];
#pragma unroll
    for (int mf = 0; mf < 4; ++mf)
        rowA[mf] = (uint32_t)((wm * 64 + mf * 16 + (g & 1) * 8 + r) * 128);
#pragma unroll
    for (int nf2 = 0; nf2 < 2; ++nf2)
        rowB[nf2] = 16384u + (uint32_t)((wn * 32 + nf2 * 16 + (g >> 1) * 8 + r) * 128);

    float acc[4][4][4];
#pragma unroll
    for (int i = 0; i < 4; ++i)
#pragma unroll
        for (int jx = 0; jx < 4; ++jx)
#pragma unroll
            for (int e = 0; e < 4; ++e) acc[i][jx][e] = 0.f;

    // prologue: chunks 0,1
#pragma unroll
    for (int q = 0; q < 8; ++q) cp16(smbase + sOff[q], gP[q]);
    cp_commit();
#pragma unroll
    for (int q = 0; q < 8; ++q) cp16(smbase + 32768 + sOff[q], gP[q] + 128);
    cp_commit();

    for (int c = 0; c < 16; ++c) {
        if (c < 15) cp_wait1(); else cp_wait0();
        __syncthreads();

        if (c + 2 < 16) {
            uint32_t sb = smbase + (uint32_t)((c + 2) % 3) * 32768;
            const int ko = (c + 2) * 128;
#pragma unroll
            for (int q = 0; q < 8; ++q) cp16(sb + sOff[q], gP[q] + ko);
            cp_commit();
        }

        uint32_t sb = smbase + (uint32_t)(c % 3) * 32768;
#pragma unroll
        for (int kk = 0; kk < 4; ++kk) {           // 4 x K16 = K64 per chunk
            uint32_t kof = (uint32_t)kk << 5;
            uint32_t ua[4][4], ub[2][4];
#pragma unroll
            for (int mf = 0; mf < 4; ++mf)
                ldsm4(sb + rowA[mf] + ((kof + hA) ^ maskv),
                      ua[mf][0], ua[mf][1], ua[mf][2], ua[mf][3]);
#pragma unroll
            for (int nf2 = 0; nf2 < 2; ++nf2)
                ldsm4(sb + rowB[nf2] + ((kof + hB) ^ maskv),
                      ub[nf2][0], ub[nf2][1], ub[nf2][2], ub[nf2][3]);
#pragma unroll
            for (int mf = 0; mf < 4; ++mf)
#pragma unroll
                for (int nf = 0; nf < 4; ++nf)
                    mma16(acc[mf][nf], ua[mf],
                          ub[nf >> 1][(nf & 1) * 2], ub[nf >> 1][(nf & 1) * 2 + 1]);
        }
        __syncthreads();
    }

    // epilogue: exp(logit+bias), store, quad-reduced row sums -> atomic
    float bb0[4], bb1[4];
#pragma unroll
    for (int nf = 0; nf < 4; ++nf) {
        int gcol = n0 + wn * 32 + nf * 8 + 2 * (lane & 3);
        bb0[nf] = bias[gcol];
        bb1[nf] = bias[gcol + 1];
    }
#pragma unroll
    for (int mf = 0; mf < 4; ++mf) {
        int grow = m0 + wm * 64 + mf * 16 + (lane >> 2);
        float rsA = 0.f, rsB = 0.f;
#pragma unroll
        for (int nf = 0; nf < 4; ++nf) {
            int gcol = n0 + wn * 32 + nf * 8 + 2 * (lane & 3);
            float e0 = __expf(acc[mf][nf][0] + bb0[nf]);
            float e1 = __expf(acc[mf][nf][1] + bb1[nf]);
            float e2 = __expf(acc[mf][nf][2] + bb0[nf]);
            float e3 = __expf(acc[mf][nf][3] + bb1[nf]);
            *(float2*)(C + (size_t)grow * VV + gcol)       = make_float2(e0, e1);
            *(float2*)(C + (size_t)(grow + 8) * VV + gcol) = make_float2(e2, e3);
            rsA += e0 + e1;
            rsB += e2 + e3;
        }
        rsA += __shfl_xor_sync(0xffffffffu, rsA, 1);
        rsA += __shfl_xor_sync(0xffffffffu, rsA, 2);
        rsB += __shfl_xor_sync(0xffffffffu, rsB, 1);
        rsB += __shfl_xor_sync(0xffffffffu, rsB, 2);
        if ((lane & 3) == 0) {
            atomicAdd(&g_rowsum[grow], rsA);
            atomicAdd(&g_rowsum[grow + 8], rsB);
        }
    }
}

// ---------------------------------------------------------------------------
// Kernel 4: normalize pass  C[row][:] *= 1/g_rowsum[row]
// ---------------------------------------------------------------------------
__global__ __launch_bounds__(256, 4)
void norm_kernel(float* __restrict__ C)
{
    float inv = 1.0f / g_rowsum[blockIdx.x];
    float4* x = (float4*)(C + blockIdx.x * (size_t)VV);
    for (int i = threadIdx.x; i < VV / 4; i += 256) {
        float4 v = x[i];
        v.x *= inv; v.y *= inv; v.z *= inv; v.w *= inv;
        x[i] = v;
    }
}

// ---------------------------------------------------------------------------
extern "C" void kernel_launch(void* const* d_in, const int* in_sizes, int n_in,
                              void* d_out, int out_size)
{
    const int*   x       = (const int*)  d_in[0];
    const float* embed_f = (const float*)d_in[1];
    const float* Wh_f    = (const float*)d_in[2];
    const float* bh_f    = (const float*)d_in[3];
    const float* embed_b = (const float*)d_in[4];
    const float* Wh_b    = (const float*)d_in[5];
    const float* bh_b    = (const float*)d_in[6];
    const float* Wout    = (const float*)d_in[7];
    const float* bout    = (const float*)d_in[8];
    float* out = (float*)d_out;

    cudaFuncSetAttribute(gemm_kernel, cudaFuncAttributeMaxDynamicSharedMemorySize,
                         GSMEM);
    cudaFuncSetAttribute(rnn_kernel,
                         cudaFuncAttributeNonPortableClusterSizeAllowed, 1);

    gather_kernel<<<2 * TT * NB, 128>>>(x, embed_f, embed_b);
    transpose_kernel<<<dim3(VV / 32, 1024 / 32), 256>>>(Wout);
    rnn_kernel<<<2 * CLU, 256>>>(Wh_f, Wh_b, bh_f, bh_b, out);
    gemm_kernel<<<dim3(MROWS / 128, VV / 128), 256, GSMEM>>>(bout, out);
    norm_kernel<<<MROWS, 256>>>(out);
}

// round 16
// speedup vs baseline: 1.3774x; 1.0075x over previous
#include <cuda_runtime.h>
#include <cuda_bf16.h>
#include <cstdint>

// Problem constants
#define NB   4
#define TT   1024
#define VV   32000
#define HH   512
#define MROWS (NB*TT)            // 4096
#define YSIZE ((size_t)MROWS*VV) // 131072000

#define CLU  16                  // cluster size per direction
#define JPC  (HH/CLU)            // 32 j-columns per CTA
#define KSL  8                   // K-slices per CTA
#define ISL  (HH/KSL)            // 64 i-elements per slice

// Scratch (allocation-free rule -> __device__ globals)
__device__ float         g_xh[2u*TT*NB*HH];        // [dir][s][n][j] 16 MB
__device__ __nv_bfloat16 g_z[(size_t)MROWS*2*HH];  // [m][k] bf16 A-matrix, 8 MB
__device__ __nv_bfloat16 g_Wt[(size_t)VV*1024];    // Wout^T [n][k] bf16, 64 MB
__device__ float         g_rowsum[MROWS];          // softmax denominators

// ---------------------------------------------------------------------------
// helpers
// ---------------------------------------------------------------------------
__device__ __forceinline__ unsigned smem_u32(const void* p)
{
    unsigned a;
    asm("{ .reg .u64 t; cvta.to.shared.u64 t, %1; cvt.u32.u64 %0, t; }"
        : "=r"(a) : "l"(p));
    return a;
}

__device__ __forceinline__ uint32_t swz(uint32_t o) { return o ^ ((o >> 3) & 0x70); }

__device__ __forceinline__ void cp16(uint32_t saddr, const void* gaddr)
{
    asm volatile("cp.async.cg.shared.global [%0], [%1], 16;"
                 :: "r"(saddr), "l"(gaddr) : "memory");
}
__device__ __forceinline__ void cp_commit()
{
    asm volatile("cp.async.commit_group;" ::: "memory");
}
__device__ __forceinline__ void cp_wait1()
{
    asm volatile("cp.async.wait_group 1;" ::: "memory");
}
__device__ __forceinline__ void cp_wait0()
{
    asm volatile("cp.async.wait_group 0;" ::: "memory");
}

__device__ __forceinline__ void ldsm4(uint32_t addr, uint32_t& r0, uint32_t& r1,
                                      uint32_t& r2, uint32_t& r3)
{
    asm volatile("ldmatrix.sync.aligned.m8n8.x4.shared.b16 {%0,%1,%2,%3}, [%4];"
                 : "=r"(r0), "=r"(r1), "=r"(r2), "=r"(r3) : "r"(addr));
}

// bf16 mma: m16n8k16, fp32 accumulate
__device__ __forceinline__ void mma16(float* d, const uint32_t* a,
                                      uint32_t b0, uint32_t b1)
{
    asm volatile("mma.sync.aligned.m16n8k16.row.col.f32.bf16.bf16.f32 "
                 "{%0,%1,%2,%3}, {%4,%5,%6,%7}, {%8,%9}, {%0,%1,%2,%3};"
                 : "+f"(d[0]), "+f"(d[1]), "+f"(d[2]), "+f"(d[3])
                 : "r"(a[0]), "r"(a[1]), "r"(a[2]), "r"(a[3]), "r"(b0), "r"(b1));
}

__device__ __forceinline__ void mbar_wait_cluster(uint32_t a, uint32_t ph)
{
    asm volatile("{\n\t.reg .pred P;\n\tWL%=:\n\t"
                 "mbarrier.try_wait.parity.acquire.cluster.shared::cta.b64 P, [%0], %1, 0x989680;\n\t"
                 "@!P bra WL%=;\n\t}"
                 :: "r"(a), "r"(ph) : "memory");
}

// ---------------------------------------------------------------------------
// Kernel 1: embedding gather (+ rowsum zeroing folded in)
// ---------------------------------------------------------------------------
__global__ __launch_bounds__(128)
void gather_kernel(const int* __restrict__ x,
                   const float* __restrict__ Ef,
                   const float* __restrict__ Eb)
{
    int b   = blockIdx.x;
    if (b < 32) g_rowsum[b * 128 + threadIdx.x] = 0.f;
    int dir = b >> 12;
    int s   = (b >> 2) & 1023;
    int n   = b & 3;
    int t   = dir ? (TT - 1 - s) : s;
    int tok = x[n * TT + t];
    const float4* src = (const float4*)((dir ? Eb : Ef) + (size_t)tok * HH);
    float4* dst = (float4*)(g_xh + ((size_t)(dir * TT + s) * NB + n) * HH);
    dst[threadIdx.x] = src[threadIdx.x];
}

// ---------------------------------------------------------------------------
// Kernel 1b: transpose Wout[k][n] -> g_Wt[n][k], bf16-rounded at write
// ---------------------------------------------------------------------------
__global__ __launch_bounds__(256)
void transpose_kernel(const float* __restrict__ Wout)
{
    __shared__ float t[32][33];
    int n0 = blockIdx.x * 32;
    int k0 = blockIdx.y * 32;
    int tx = threadIdx.x & 31, ty = threadIdx.x >> 5;
#pragma unroll
    for (int r = 0; r < 32; r += 8)
        t[ty + r][tx] = Wout[(size_t)(k0 + ty + r) * VV + n0 + tx];
    __syncthreads();
#pragma unroll
    for (int r = 0; r < 32; r += 8)
        g_Wt[(size_t)(n0 + ty + r) * 1024 + k0 + tx] = __float2bfloat16(t[tx][ty + r]);
}

// ---------------------------------------------------------------------------
// Kernel 2: bidirectional RNN scan, cluster-of-16 per direction.
// st.async + split-half mbarriers: senders 0-7 arrive half A, 8-15 half B
// (4096 B each). Consumer warp ks waits only on the half that feeds its
// i-range: ks<4 -> A, ks>=4 -> B. Rearm: tid0 (warp0) A, tid128 (warp4) B.
// ---------------------------------------------------------------------------
__global__ __cluster_dims__(CLU, 1, 1) __launch_bounds__(256, 1)
void rnn_kernel(const float* __restrict__ Wh_f, const float* __restrict__ Wh_b,
                const float* __restrict__ bh_f, const float* __restrict__ bh_b,
                float* __restrict__ out)
{
    __shared__ float    h_s[2][HH][NB];       // [buf][j][n], 16 KB
    __shared__ float    red[2][KSL][JPC][4];  // [buf][kslice][jj][n], 8 KB
    __shared__ uint64_t mbar[2][2];           // [buf][half]

    int tid = threadIdx.x;
    int jj  = tid & 31;
    int ks  = tid >> 5;            // 0..7
    unsigned crank;
    asm("mov.u32 %0, %%cluster_ctarank;" : "=r"(crank));
    int dir = blockIdx.x >> 4;
    int j   = (int)crank * JPC + jj;

    const float* Wh = dir ? Wh_b : Wh_f;
    const float* bh = dir ? bh_b : bh_f;

    // register-resident packed weight slice: {w,w} for Wh[ks*64+u][j]
    uint64_t wpk[ISL];
#pragma unroll
    for (int u = 0; u < ISL; ++u) {
        uint32_t wu = __float_as_uint(Wh[(size_t)(ks * ISL + u) * HH + j]);
        asm("mov.b64 %0, {%1, %1};" : "=l"(wpk[u]) : "r"(wu));
    }
    float bhv = bh[j];

    // init: zero h buffer 0, init + pre-arm all 4 mbarriers (4096 B per half)
    for (int i = tid; i < HH * NB; i += 256) ((float*)h_s[0])[i] = 0.f;
    if (tid == 0) {
        uint32_t mb = smem_u32(&mbar[0][0]);
#pragma unroll
        for (int q = 0; q < 4; ++q)
            asm volatile("mbarrier.init.shared.b64 [%0], 1;"
                         :: "r"(mb + q * 8) : "memory");
        asm volatile("fence.mbarrier_init.release.cluster;" ::: "memory");
#pragma unroll
        for (int q = 0; q < 4; ++q)
            asm volatile("mbarrier.arrive.expect_tx.shared.b64 _, [%0], %1;"
                         :: "r"(mb + q * 8), "r"(4096u) : "memory");
    }
    __syncthreads();
    asm volatile("barrier.cluster.arrive.aligned;" ::: "memory");
    asm volatile("barrier.cluster.wait.aligned;"   ::: "memory");

    // remote base addresses, staggered start per rank
    uint32_t hloc = smem_u32(&h_s[0][0][0]);
    uint32_t mloc = smem_u32(&mbar[0][0]);
    uint32_t rh[CLU], rm[CLU];
#pragma unroll
    for (int c = 0; c < CLU; ++c) {
        int cc = (int)((crank + c) & (CLU - 1));
        asm("mapa.shared::cluster.u32 %0, %1, %2;" : "=r"(rh[c]) : "r"(hloc), "r"(cc));
        asm("mapa.shared::cluster.u32 %0, %1, %2;" : "=r"(rm[c]) : "r"(mloc), "r"(cc));
    }

    const float* xh_base = g_xh + (size_t)dir * TT * NB * HH;
    uint32_t myhalf  = (uint32_t)(ks >> 2) * 8;     // consumer half offset
    uint32_t sndhalf = (crank >> 3) * 8;            // producer half offset
    uint32_t ph0 = 0, ph1 = 0;

    for (int s = 0; s < TT; ++s) {
        int rb = s & 1;        // h read buffer / red buffer
        int wb = rb ^ 1;       // h write buffer

        if (s > 0) {
            uint32_t mb = mloc + (uint32_t)rb * 16 + myhalf;
            mbar_wait_cluster(mb, rb ? ph1 : ph0);
            if (tid == 0 || tid == 128)
                asm volatile("mbarrier.arrive.expect_tx.shared.b64 _, [%0], %1;"
                             :: "r"(mb), "r"(4096u) : "memory");
            if (rb) ph1 ^= 1; else ph0 ^= 1;
        }

        // prefetch xh for phase 2 (threads 0..31 only)
        float xv0 = 0.f, xv1 = 0.f, xv2 = 0.f, xv3 = 0.f;
        if (tid < JPC) {
            const float* xp = xh_base + (size_t)s * NB * HH + j;
            xv0 = xp[0]; xv1 = xp[HH]; xv2 = xp[2 * HH]; xv3 = xp[3 * HH];
        }

        // phase 1: packed partial dot for 4 batch rows over 64 K-elements
        uint64_t a01 = 0ull, a23 = 0ull;
        uint32_t hb = hloc + (uint32_t)rb * (HH * NB * 4) + (uint32_t)(ks * ISL) * 16;
#pragma unroll
        for (int u = 0; u < ISL; ++u) {
            uint64_t h01, h23;
            asm("ld.shared.v2.b64 {%0,%1}, [%2];"
                : "=l"(h01), "=l"(h23) : "r"(hb + u * 16));
            asm("fma.rn.f32x2 %0, %1, %2, %0;" : "+l"(a01) : "l"(h01), "l"(wpk[u]));
            asm("fma.rn.f32x2 %0, %1, %2, %0;" : "+l"(a23) : "l"(h23), "l"(wpk[u]));
        }
        {
            uint32_t rw = smem_u32(&red[rb][ks][jj][0]);
            asm volatile("st.shared.v2.b64 [%0], {%1,%2};"
                         :: "r"(rw), "l"(a01), "l"(a23) : "memory");
        }
        __syncthreads();

        // phase 2: thread jj (tid<32) handles column j, all 4 batches
        if (tid < JPC) {
            float4 p0 = *(const float4*)&red[rb][0][jj][0];
            float4 p1 = *(const float4*)&red[rb][1][jj][0];
            float4 p2 = *(const float4*)&red[rb][2][jj][0];
            float4 p3 = *(const float4*)&red[rb][3][jj][0];
            float4 p4 = *(const float4*)&red[rb][4][jj][0];
            float4 p5 = *(const float4*)&red[rb][5][jj][0];
            float4 p6 = *(const float4*)&red[rb][6][jj][0];
            float4 p7 = *(const float4*)&red[rb][7][jj][0];
            float h0 = tanhf(((p0.x + p1.x) + (p2.x + p3.x)) +
                             ((p4.x + p5.x) + (p6.x + p7.x)) + xv0 + bhv);
            float h1 = tanhf(((p0.y + p1.y) + (p2.y + p3.y)) +
                             ((p4.y + p5.y) + (p6.y + p7.y)) + xv1 + bhv);
            float h2 = tanhf(((p0.z + p1.z) + (p2.z + p3.z)) +
                             ((p4.z + p5.z) + (p6.z + p7.z)) + xv2 + bhv);
            float h3 = tanhf(((p0.w + p1.w) + (p2.w + p3.w)) +
                             ((p4.w + p5.w) + (p6.w + p7.w)) + xv3 + bhv);

            // broadcast FIRST: the whole cluster waits on these bytes
            if (s < TT - 1) {
                uint32_t off = (uint32_t)wb * (HH * NB * 4) + (uint32_t)j * 16;
                uint32_t mof = (uint32_t)wb * 16 + sndhalf;
                uint32_t u0 = __float_as_uint(h0), u1 = __float_as_uint(h1);
                uint32_t u2 = __float_as_uint(h2), u3 = __float_as_uint(h3);
#pragma unroll
                for (int c = 0; c < CLU; ++c)
                    asm volatile(
                        "st.async.shared::cluster.mbarrier::complete_tx::bytes.v4.b32 "
                        "[%0], {%1,%2,%3,%4}, [%5];"
                        :: "r"(rh[c] + off), "r"(u0), "r"(u1), "r"(u2), "r"(u3),
                           "r"(rm[c] + mof) : "memory");
            }

            // global stores off the critical path (bf16 for the GEMM A-matrix)
            int t_out = dir ? (TT - 1 - s) : s;
            size_t zb = (size_t)t_out * (2 * HH) + dir * HH + j;
            g_z[zb]                           = __float2bfloat16(h0);
            g_z[zb + (size_t)TT * 2 * HH]     = __float2bfloat16(h1);
            g_z[zb + (size_t)2 * TT * 2 * HH] = __float2bfloat16(h2);
            g_z[zb + (size_t)3 * TT * 2 * HH] = __float2bfloat16(h3);
            if (s == TT - 1) {
                size_t ob = YSIZE + (size_t)dir * (NB * HH) + j;
                out[ob]          = h0;
                out[ob + HH]     = h1;
                out[ob + 2 * HH] = h2;
                out[ob + 3 * HH] = h3;
            }
        }
    }
}

// ---------------------------------------------------------------------------
// Kernel 3: bf16 mma.sync GEMM,  C = exp(z @ Wt^T + bias), row sums -> g_rowsum
// CTA tile 128x128, K chunk 64 (128B bf16 rows), 16 chunks, 3-stage cp.async,
// SINGLE syncthreads per chunk, 2 CTAs/SM co-residency.
// ---------------------------------------------------------------------------
#define GSMEM (3*32768 + 1024)

__global__ __launch_bounds__(256)
void gemm_kernel(const float* __restrict__ bias, float* __restrict__ C)
{
    extern __shared__ char dsm[];
    uint32_t smbase = (smem_u32(dsm) + 1023) & ~1023u;

    int tid  = threadIdx.x;
    int lane = tid & 31, w = tid >> 5;
    int wm = w >> 2, wn = w & 3;
    int m0 = blockIdx.x * 128, n0 = blockIdx.y * 128;

    // loader: 4 A + 4 B 16B copies per thread per chunk (32KB/chunk)
    uint32_t sOff[8];
    const char* gP[8];
#pragma unroll
    for (int q = 0; q < 4; ++q) {
        int idx = q * 256 + tid;
        int row = idx >> 3, c4 = idx & 7;
        sOff[q]     = swz((uint32_t)(row * 128 + c4 * 16));
        sOff[q + 4] = 16384u + sOff[q];
        gP[q]     = (const char*)g_z  + (size_t)(m0 + row) * 2048 + c4 * 16;
        gP[q + 4] = (const char*)g_Wt + (size_t)(n0 + row) * 2048 + c4 * 16;
    }

    int r = lane & 7, g = lane >> 3;
    uint32_t maskv = (uint32_t)r << 4;
    uint32_t hA = (uint32_t)(g >> 1) << 4;
    uint32_t hB = (uint32_t)(g & 1) << 4;
    uint32_t rowA[4], rowB[2];
#pragma unroll
    for (int mf = 0; mf < 4; ++mf)
        rowA[mf] = (uint32_t)((wm * 64 + mf * 16 + (g & 1) * 8 + r) * 128);
#pragma unroll
    for (int nf2 = 0; nf2 < 2; ++nf2)
        rowB[nf2] = 16384u + (uint32_t)((wn * 32 + nf2 * 16 + (g >> 1) * 8 + r) * 128);

    float acc[4][4][4];
#pragma unroll
    for (int i = 0; i < 4; ++i)
#pragma unroll
        for (int jx = 0; jx < 4; ++jx)
#pragma unroll
            for (int e = 0; e < 4; ++e) acc[i][jx][e] = 0.f;

    // prologue: chunks 0,1
#pragma unroll
    for (int q = 0; q < 8; ++q) cp16(smbase + sOff[q], gP[q]);
    cp_commit();
#pragma unroll
    for (int q = 0; q < 8; ++q) cp16(smbase + 32768 + sOff[q], gP[q] + 128);
    cp_commit();

    for (int c = 0; c < 16; ++c) {
        if (c < 15) cp_wait1(); else cp_wait0();
        __syncthreads();

        if (c + 2 < 16) {
            uint32_t sb = smbase + (uint32_t)((c + 2) % 3) * 32768;
            const int ko = (c + 2) * 128;
#pragma unroll
            for (int q = 0; q < 8; ++q) cp16(sb + sOff[q], gP[q] + ko);
            cp_commit();
        }

        uint32_t sb = smbase + (uint32_t)(c % 3) * 32768;
#pragma unroll
        for (int kk = 0; kk < 4; ++kk) {           // 4 x K16 = K64 per chunk
            uint32_t kof = (uint32_t)kk << 5;
            uint32_t ua[4][4], ub[2][4];
#pragma unroll
            for (int mf = 0; mf < 4; ++mf)
                ldsm4(sb + rowA[mf] + ((kof + hA) ^ maskv),
                      ua[mf][0], ua[mf][1], ua[mf][2], ua[mf][3]);
#pragma unroll
            for (int nf2 = 0; nf2 < 2; ++nf2)
                ldsm4(sb + rowB[nf2] + ((kof + hB) ^ maskv),
                      ub[nf2][0], ub[nf2][1], ub[nf2][2], ub[nf2][3]);
#pragma unroll
            for (int mf = 0; mf < 4; ++mf)
#pragma unroll
                for (int nf = 0; nf < 4; ++nf)
                    mma16(acc[mf][nf], ua[mf],
                          ub[nf >> 1][(nf & 1) * 2], ub[nf >> 1][(nf & 1) * 2 + 1]);
        }
    }

    // epilogue: exp(logit+bias), store, quad-reduced row sums -> atomic
    float bb0[4], bb1[4];
#pragma unroll
    for (int nf = 0; nf < 4; ++nf) {
        int gcol = n0 + wn * 32 + nf * 8 + 2 * (lane & 3);
        bb0[nf] = bias[gcol];
        bb1[nf] = bias[gcol + 1];
    }
#pragma unroll
    for (int mf = 0; mf < 4; ++mf) {
        int grow = m0 + wm * 64 + mf * 16 + (lane >> 2);
        float rsA = 0.f, rsB = 0.f;
#pragma unroll
        for (int nf = 0; nf < 4; ++nf) {
            int gcol = n0 + wn * 32 + nf * 8 + 2 * (lane & 3);
            float e0 = __expf(acc[mf][nf][0] + bb0[nf]);
            float e1 = __expf(acc[mf][nf][1] + bb1[nf]);
            float e2 = __expf(acc[mf][nf][2] + bb0[nf]);
            float e3 = __expf(acc[mf][nf][3] + bb1[nf]);
            *(float2*)(C + (size_t)grow * VV + gcol)       = make_float2(e0, e1);
            *(float2*)(C + (size_t)(grow + 8) * VV + gcol) = make_float2(e2, e3);
            rsA += e0 + e1;
            rsB += e2 + e3;
        }
        rsA += __shfl_xor_sync(0xffffffffu, rsA, 1);
        rsA += __shfl_xor_sync(0xffffffffu, rsA, 2);
        rsB += __shfl_xor_sync(0xffffffffu, rsB, 1);
        rsB += __shfl_xor_sync(0xffffffffu, rsB, 2);
        if ((lane & 3) == 0) {
            atomicAdd(&g_rowsum[grow], rsA);
            atomicAdd(&g_rowsum[grow + 8], rsB);
        }
    }
}

// ---------------------------------------------------------------------------
// Kernel 4: normalize pass  C[row][:] *= 1/g_rowsum[row]
// ---------------------------------------------------------------------------
__global__ __launch_bounds__(256, 4)
void norm_kernel(float* __restrict__ C)
{
    float inv = 1.0f / g_rowsum[blockIdx.x];
    float4* x = (float4*)(C + blockIdx.x * (size_t)VV);
    for (int i = threadIdx.x; i < VV / 4; i += 256) {
        float4 v = x[i];
        v.x *= inv; v.y *= inv; v.z *= inv; v.w *= inv;
        x[i] = v;
    }
}

// ---------------------------------------------------------------------------
extern "C" void kernel_launch(void* const* d_in, const int* in_sizes, int n_in,
                              void* d_out, int out_size)
{
    const int*   x       = (const int*)  d_in[0];
    const float* embed_f = (const float*)d_in[1];
    const float* Wh_f    = (const float*)d_in[2];
    const float* bh_f    = (const float*)d_in[3];
    const float* embed_b = (const float*)d_in[4];
    const float* Wh_b    = (const float*)d_in[5];
    const float* bh_b    = (const float*)d_in[6];
    const float* Wout    = (const float*)d_in[7];
    const float* bout    = (const float*)d_in[8];
    float* out = (float*)d_out;

    cudaFuncSetAttribute(gemm_kernel, cudaFuncAttributeMaxDynamicSharedMemorySize,
                         GSMEM);
    cudaFuncSetAttribute(rnn_kernel,
                         cudaFuncAttributeNonPortableClusterSizeAllowed, 1);

    gather_kernel<<<2 * TT * NB, 128>>>(x, embed_f, embed_b);
    transpose_kernel<<<dim3(VV / 32, 1024 / 32), 256>>>(Wout);
    rnn_kernel<<<2 * CLU, 256>>>(Wh_f, Wh_b, bh_f, bh_b, out);
    gemm_kernel<<<dim3(MROWS / 128, VV / 128), 256, GSMEM>>>(bout, out);
    norm_kernel<<<MROWS, 256>>>(out);
}